// round 16
// baseline (speedup 1.0000x reference)
#include <cuda_runtime.h>
#include <cuda_fp16.h>
#include <cstdint>

// Problem constants
#define NB 2        // B
#define LL 16       // L
#define NN 10000    // N
#define FIN 8
#define HH 64       // H
#define PP 12       // P
#define EE 80000    // E
// Only l = 14,15 feed out[:, :, -1]. Slot s = b*2 + (l-14); row = [n][s][64].
#define SLOTS 4
#define ROWF (SLOTS * HH)   // 256 values per node row
#define CAP 64              // per-node edge bucket capacity (max deg ~35)

// Scratch
__device__ __align__(16) __half g_h16[(size_t)NN * ROWF];
__device__ int g_cnt[NN];                                // zero-init; K2 cleans
__device__ __align__(8) int2 g_edge[(size_t)NN * CAP];   // {col, val_bits}

// ---- packed fp32x2 helpers (Blackwell FFMA2; fp32-exact) ----
__device__ __forceinline__ unsigned long long fma2(unsigned long long a,
                                                   unsigned long long b,
                                                   unsigned long long c) {
    unsigned long long d;
    asm("fma.rn.f32x2 %0, %1, %2, %3;" : "=l"(d) : "l"(a), "l"(b), "l"(c));
    return d;
}
__device__ __forceinline__ unsigned long long pack2(float lo, float hi) {
    unsigned long long r;
    asm("mov.b64 %0, {%1, %2};" : "=l"(r) : "f"(lo), "f"(hi));
    return r;
}
__device__ __forceinline__ float sum2(unsigned long long v) {
    float lo, hi;
    asm("mov.b64 {%0, %1}, %2;" : "=f"(lo), "=f"(hi) : "l"(v));
    return lo + hi;
}

// ---------------------------------------------------------------------------
// K1: proj + binning, FAT blocks (proven ~2us): 250 blocks x 256 thr;
// each warp handles 5 nodes; binning strided over 64000 threads.
// ---------------------------------------------------------------------------
#define P_BLOCKS 250
#define P_WARPS_TOT (P_BLOCKS * 8)     // 2000
#define P_NPW 5                        // 2000*5 = 10000 exact

__global__ void k_proj_bin(const float* __restrict__ x,
                           const float* __restrict__ W_in,
                           const float* __restrict__ b_in,
                           const int* __restrict__ erow,
                           const int* __restrict__ ecol,
                           const float* __restrict__ evals) {
    __shared__ float sW[FIN * HH];
    __shared__ float sb[HH];
    int tid = threadIdx.x;
    int gid = blockIdx.x * blockDim.x + tid;     // < 64000

    for (int i = tid; i < FIN * HH; i += blockDim.x) sW[i] = W_in[i];
    if (tid < HH) sb[tid] = b_in[tid];
    __syncthreads();

    int warp = blockIdx.x * 8 + (tid >> 5);      // < 2000
    int lane = tid & 31;
    int hh0 = lane * 2;
    int hh1 = hh0 + 1;

    #pragma unroll
    for (int j = 0; j < P_NPW; j++) {
        int n = warp + j * P_WARPS_TOT;          // < 10000
        #pragma unroll
        for (int s = 0; s < SLOTS; s++) {
            int b = s >> 1;
            int l = 14 + (s & 1);
            const float4* xr = reinterpret_cast<const float4*>(
                x + (((size_t)b * LL + l) * NN + n) * FIN);
            float4 x0 = __ldg(xr);               // warp-broadcast 32B row
            float4 x1 = __ldg(xr + 1);
            float xv[8] = {x0.x, x0.y, x0.z, x0.w, x1.x, x1.y, x1.z, x1.w};

            float acc0 = sb[hh0];
            float acc1 = sb[hh1];
            #pragma unroll
            for (int f = 0; f < 8; f++) {
                acc0 = fmaf(xv[f], sW[f * HH + hh0], acc0);
                acc1 = fmaf(xv[f], sW[f * HH + hh1], acc1);
            }
            __half2* hrow = reinterpret_cast<__half2*>(
                g_h16 + ((size_t)n * SLOTS + s) * HH);
            hrow[lane] = __floats2half2_rn(fmaxf(acc0, 0.0f), fmaxf(acc1, 0.0f));
        }
    }

    // edge binning (tail work, strided)
    for (int e = gid; e < EE; e += P_BLOCKS * 256) {
        int r = __ldg(erow + e);
        int rank = atomicAdd(&g_cnt[r], 1);
        if (rank < CAP)
            g_edge[(size_t)r * CAP + rank] =
                make_int2(__ldg(ecol + e), __float_as_int(__ldg(evals + e)));
    }
}

// ---------------------------------------------------------------------------
// K2: fused gather + TCN-last + output. NEW geometry: ONE 1024-thread block
// per SM (32 warps), 2 nodes = 4 pairs/warp, grid 157 (157*64 = 10048).
// smem weights shared by all 32 warps; su4 = 64KB (scales with pairs, not
// warps). 2x warps/SM vs R12 at near-constant total work.
// su4 float layout per (warp,pair): idx = (h>>1)*4 + tap*2 + (h&1)
// sWt4 float4 [ip][o] = {w0[2ip], w0[2ip+1], w1[2ip], w1[2ip+1]}
// ---------------------------------------------------------------------------
#define K2_WARPS 32
#define K2_THREADS 1024
#define K2_NPW 2                                          // nodes per warp
#define K2_GRID 157                                       // 157*32*2 = 10048

#define SM_WT 0
#define SM_SU (SM_WT + 32 * 64 * 16)                      // 32768
#define SM_WO (SM_SU + K2_WARPS * 4 * 32 * 16)            // +65536 = 98304
#define SM_BT (SM_WO + PP * 64 * 4)                       // +3072  = 101376
#define SM_BO (SM_BT + 64 * 4)                            // +256   = 101632
#define SM_TOT (SM_BO + 64)                               //        = 101696

__global__ void __launch_bounds__(K2_THREADS, 1)
k_gf(const float* __restrict__ W_tcn,
     const float* __restrict__ b_tcn,
     const float* __restrict__ W_out,
     const float* __restrict__ b_out,
     float* __restrict__ out) {
    extern __shared__ char dsm[];
    float4 (*sWt4)[64] = reinterpret_cast<float4(*)[64]>(dsm + SM_WT);
    float4 (*su4)[4][32] = reinterpret_cast<float4(*)[4][32]>(dsm + SM_SU);
    float*  sWtF = reinterpret_cast<float*>(dsm + SM_WT);
    float*  sWoT = reinterpret_cast<float*>(dsm + SM_WO);
    float*  sbt  = reinterpret_cast<float*>(dsm + SM_BT);
    float*  sbo  = reinterpret_cast<float*>(dsm + SM_BO);

    int tid = threadIdx.x;
    int w = tid >> 5, lane = tid & 31;

    // ---- weight staging (coalesced reads, LDS-side transpose) ----
    // sWt4[ip][o] = W_tcn[o*192 + {6ip+0, 6ip+3, 6ip+1, 6ip+4}]
    for (int o = w; o < 64; o += K2_WARPS) {
        const float* wr = W_tcn + o * 192;
        #pragma unroll
        for (int j = 0; j < 6; j++) {
            int f = lane + 32 * j;
            float val = __ldg(wr + f);
            int ip = f / 6;
            int c  = f - ip * 6;               // 0..5
            int comp = (c == 0) ? 0 : (c == 3) ? 1 : (c == 1) ? 2 : (c == 4) ? 3 : -1;
            if (comp >= 0) sWtF[ip * 256 + o * 4 + comp] = val;
        }
    }
    for (int t = tid; t < 64 * PP; t += K2_THREADS) {
        float v = __ldg(W_out + t);
        int o = t / PP, p = t - o * PP;
        sWoT[p * 64 + o] = v;
    }
    if (tid < 64) sbt[tid] = b_tcn[tid];
    if (tid >= 64 && tid < 64 + PP) sbo[tid - 64] = b_out[tid - 64];
    __syncthreads();

    int wg = blockIdx.x * K2_WARPS + w;       // 0..5023
    int nBase = wg * K2_NPW;                  // 10048 >= NN
    if (nBase >= NN) return;

    // ---- hoisted per-node metadata ----
    int deg[K2_NPW];
    const int2* ep[K2_NPW];
    #pragma unroll
    for (int m = 0; m < K2_NPW; m++) {
        int node = nBase + m;
        int nd = node < NN ? node : NN - 1;
        int d = g_cnt[nd];
        deg[m] = d > CAP ? CAP : d;
        ep[m] = g_edge + (size_t)nd * CAP;
    }

    // ---- gather 2 nodes, 4-edge groups (reg budget: 64/thread) ----
    const float4* hb = reinterpret_cast<const float4*>(g_h16);  // 32 f4 / row
    #pragma unroll
    for (int m = 0; m < K2_NPW; m++) {
        float a[8];
        #pragma unroll
        for (int i = 0; i < 8; i++) a[i] = 0.0f;

        for (int k = 0; k < deg[m]; k += 4) {
            int   c[4];
            float v[4];
            #pragma unroll
            for (int j = 0; j < 4; j++) {
                int kk = k + j < deg[m] ? k + j : deg[m] - 1;
                int2 e = __ldg(ep[m] + kk);           // uniform, L1-hot
                c[j] = e.x;
                v[j] = (k + j < deg[m]) ? __int_as_float(e.y) : 0.0f;
            }
            float4 h4[4];
            #pragma unroll
            for (int j = 0; j < 4; j++)
                h4[j] = __ldg(hb + (size_t)c[j] * 32 + lane);
            #pragma unroll
            for (int j = 0; j < 4; j++) {
                const __half2* hp = reinterpret_cast<const __half2*>(&h4[j]);
                #pragma unroll
                for (int q = 0; q < 4; q++) {
                    float2 f = __half22float2(hp[q]);
                    a[q * 2 + 0] = fmaf(f.x, v[j], a[q * 2 + 0]);
                    a[q * 2 + 1] = fmaf(f.y, v[j], a[q * 2 + 1]);
                }
            }
        }

        // scatter relu(a) into su4: lane owns row values f = 8*lane + j
        #pragma unroll
        for (int j = 0; j < 8; j++) {
            int f = lane * 8 + j;
            int s = f >> 6;
            int h = f & 63;
            int b = s >> 1;
            int tap = s & 1;
            float* dst = reinterpret_cast<float*>(&su4[w][m * 2 + b][0]);
            dst[(h >> 1) * 4 + tap * 2 + (h & 1)] = fmaxf(a[j], 0.0f);
        }
    }
    if (lane < K2_NPW && nBase + lane < NN) g_cnt[nBase + lane] = 0;
    __syncwarp();

    // ---- z-stage: 4 pairs, packed f32x2 (exact fp32), smem weights ----
    unsigned long long z0[4], z1[4];
    #pragma unroll
    for (int pp = 0; pp < 4; pp++) {
        z0[pp] = pack2(sbt[lane], 0.0f);
        z1[pp] = pack2(sbt[lane + 32], 0.0f);
    }
    #pragma unroll 4
    for (int ip = 0; ip < 32; ip++) {
        ulonglong2 wA = *reinterpret_cast<const ulonglong2*>(&sWt4[ip][lane]);
        ulonglong2 wB = *reinterpret_cast<const ulonglong2*>(&sWt4[ip][lane + 32]);
        #pragma unroll
        for (int pp = 0; pp < 4; pp++) {
            ulonglong2 u = *reinterpret_cast<const ulonglong2*>(&su4[w][pp][ip]);
            z0[pp] = fma2(u.x, wA.x, z0[pp]);   // tap0 pair
            z0[pp] = fma2(u.y, wA.y, z0[pp]);   // tap1 pair
            z1[pp] = fma2(u.x, wB.x, z1[pp]);
            z1[pp] = fma2(u.y, wB.y, z1[pp]);
        }
    }
    __syncwarp();
    #pragma unroll
    for (int pp = 0; pp < 4; pp++) {
        float* zf = reinterpret_cast<float*>(&su4[w][pp][0]);
        zf[lane]      = fmaxf(sum2(z0[pp]), 0.0f);
        zf[lane + 32] = fmaxf(sum2(z1[pp]), 0.0f);
    }
    __syncwarp();

    // ---- y-stage: 48 outputs (4 pairs x 12) in 2 lane-rounds ----
    #pragma unroll
    for (int r = 0; r < 2; r++) {
        int q = lane + r * 32;               // 0..63
        if (q < 4 * PP) {
            int pp = q / PP;
            int p  = q - pp * PP;
            unsigned long long y2 = pack2(sbo[p], 0.0f);
            const ulonglong2* z4 =
                reinterpret_cast<const ulonglong2*>(&su4[w][pp][0]);
            const ulonglong2* w4 =
                reinterpret_cast<const ulonglong2*>(sWoT + p * 64);
            #pragma unroll 4
            for (int oc = 0; oc < 16; oc++) {
                ulonglong2 zz = z4[oc];
                ulonglong2 ww = w4[oc];
                y2 = fma2(zz.x, ww.x, y2);
                y2 = fma2(zz.y, ww.y, y2);
            }
            int node = nBase + (pp >> 1);
            int b = pp & 1;
            if (node < NN)
                out[((size_t)b * PP + p) * NN + node] = sum2(y2);
        }
    }
}

// ---------------------------------------------------------------------------
extern "C" void kernel_launch(void* const* d_in, const int* in_sizes, int n_in,
                              void* d_out, int out_size) {
    const float* x     = (const float*)d_in[0];
    const int*   row   = (const int*)  d_in[1];
    const int*   col   = (const int*)  d_in[2];
    const float* vals  = (const float*)d_in[3];
    const float* W_in  = (const float*)d_in[4];
    const float* b_in  = (const float*)d_in[5];
    const float* W_tcn = (const float*)d_in[6];
    const float* b_tcn = (const float*)d_in[7];
    const float* W_out = (const float*)d_in[8];
    const float* b_out = (const float*)d_in[9];
    float* out = (float*)d_out;

    static bool attr_set = false;
    if (!attr_set) {
        cudaFuncSetAttribute(k_gf,
                             cudaFuncAttributeMaxDynamicSharedMemorySize, SM_TOT);
        attr_set = true;
    }

    k_proj_bin<<<P_BLOCKS, 256>>>(x, W_in, b_in, row, col, vals);
    k_gf<<<K2_GRID, K2_THREADS, SM_TOT>>>(W_tcn, b_tcn, W_out, b_out, out);
}

// round 17
// speedup vs baseline: 2.0315x; 2.0315x over previous
#include <cuda_runtime.h>
#include <cuda_fp16.h>
#include <cstdint>

// Problem constants
#define NB 2        // B
#define LL 16       // L
#define NN 10000    // N
#define FIN 8
#define HH 64       // H
#define PP 12       // P
#define EE 80000    // E
// Only l = 14,15 feed out[:, :, -1]. Slot s = b*2 + (l-14); row = [n][s][64].
#define SLOTS 4
#define ROWF (SLOTS * HH)   // 256 values per node row
#define CAP 64              // per-node edge bucket capacity (max deg ~35)

// Scratch
__device__ __align__(16) __half g_h16[(size_t)NN * ROWF];
__device__ int g_cnt[NN];                                // zero-init; K2 cleans
__device__ __align__(8) int2 g_edge[(size_t)NN * CAP];   // {col, val_bits}

// ---- packed fp32x2 helpers (Blackwell FFMA2; fp32-exact) ----
__device__ __forceinline__ unsigned long long fma2(unsigned long long a,
                                                   unsigned long long b,
                                                   unsigned long long c) {
    unsigned long long d;
    asm("fma.rn.f32x2 %0, %1, %2, %3;" : "=l"(d) : "l"(a), "l"(b), "l"(c));
    return d;
}
__device__ __forceinline__ unsigned long long pack2(float lo, float hi) {
    unsigned long long r;
    asm("mov.b64 %0, {%1, %2};" : "=l"(r) : "f"(lo), "f"(hi));
    return r;
}
__device__ __forceinline__ float sum2(unsigned long long v) {
    float lo, hi;
    asm("mov.b64 {%0, %1}, %2;" : "=f"(lo), "=f"(hi) : "l"(v));
    return lo + hi;
}

// ---------------------------------------------------------------------------
// K1: proj + binning, FAT blocks (proven ~2us): 250 blocks x 256 thr;
// each warp handles 5 nodes; binning strided over 64000 threads.
// ---------------------------------------------------------------------------
#define P_BLOCKS 250
#define P_WARPS_TOT (P_BLOCKS * 8)     // 2000
#define P_NPW 5                        // 2000*5 = 10000 exact

__global__ void k_proj_bin(const float* __restrict__ x,
                           const float* __restrict__ W_in,
                           const float* __restrict__ b_in,
                           const int* __restrict__ erow,
                           const int* __restrict__ ecol,
                           const float* __restrict__ evals) {
    __shared__ float sW[FIN * HH];
    __shared__ float sb[HH];
    int tid = threadIdx.x;
    int gid = blockIdx.x * blockDim.x + tid;     // < 64000

    for (int i = tid; i < FIN * HH; i += blockDim.x) sW[i] = W_in[i];
    if (tid < HH) sb[tid] = b_in[tid];
    __syncthreads();

    int warp = blockIdx.x * 8 + (tid >> 5);      // < 2000
    int lane = tid & 31;
    int hh0 = lane * 2;
    int hh1 = hh0 + 1;

    #pragma unroll
    for (int j = 0; j < P_NPW; j++) {
        int n = warp + j * P_WARPS_TOT;          // < 10000
        #pragma unroll
        for (int s = 0; s < SLOTS; s++) {
            int b = s >> 1;
            int l = 14 + (s & 1);
            const float4* xr = reinterpret_cast<const float4*>(
                x + (((size_t)b * LL + l) * NN + n) * FIN);
            float4 x0 = __ldg(xr);               // warp-broadcast 32B row
            float4 x1 = __ldg(xr + 1);
            float xv[8] = {x0.x, x0.y, x0.z, x0.w, x1.x, x1.y, x1.z, x1.w};

            float acc0 = sb[hh0];
            float acc1 = sb[hh1];
            #pragma unroll
            for (int f = 0; f < 8; f++) {
                acc0 = fmaf(xv[f], sW[f * HH + hh0], acc0);
                acc1 = fmaf(xv[f], sW[f * HH + hh1], acc1);
            }
            __half2* hrow = reinterpret_cast<__half2*>(
                g_h16 + ((size_t)n * SLOTS + s) * HH);
            hrow[lane] = __floats2half2_rn(fmaxf(acc0, 0.0f), fmaxf(acc1, 0.0f));
        }
    }

    // edge binning (tail work, strided)
    for (int e = gid; e < EE; e += P_BLOCKS * 256) {
        int r = __ldg(erow + e);
        int rank = atomicAdd(&g_cnt[r], 1);
        if (rank < CAP)
            g_edge[(size_t)r * CAP + rank] =
                make_int2(__ldg(ecol + e), __float_as_int(__ldg(evals + e)));
    }
}

// ---------------------------------------------------------------------------
// K2: fused gather + TCN-last + output. R15 geometry (grid 148 x 17 warps,
// 4 nodes = 8 pairs/warp, smem weights, 8-deep gather, f32x2 GEMM) with
// BANK-CONFLICT PADDING:
//   su4 pair stride 32 -> 33 float4 (528B == 16 mod 128: 8 pp bases on
//   distinct banks -> y-stage z-reads 8-way -> 1-way)
//   sWoT row stride 64 -> 68 floats (272B: w-reads ~12-way -> 2-way)
// su4 float layout per (warp,pair): idx = (h>>1)*4 + tap*2 + (h&1)
// sWt4 float4 [ip][o] = {w0[2ip], w0[2ip+1], w1[2ip], w1[2ip+1]}
// ---------------------------------------------------------------------------
#define K2_WARPS 17
#define K2_THREADS (K2_WARPS * 32)            // 544
#define SU_STRIDE 33                          // float4 per pair (padded)
#define WO_STRIDE 68                          // floats per p row (padded)

#define SM_WT 0
#define SM_SU (SM_WT + 32 * 64 * 16)                      // 32768
#define SM_WO (SM_SU + K2_WARPS * 8 * SU_STRIDE * 16)     // +71808 = 104576
#define SM_BT (SM_WO + PP * WO_STRIDE * 4)                // +3264  = 107840
#define SM_BO (SM_BT + 64 * 4)                            // +256   = 108096
#define SM_TOT (SM_BO + 64)                               //        = 108160

__global__ void __launch_bounds__(K2_THREADS, 1)
k_gf(const float* __restrict__ W_tcn,
     const float* __restrict__ b_tcn,
     const float* __restrict__ W_out,
     const float* __restrict__ b_out,
     float* __restrict__ out) {
    extern __shared__ char dsm[];
    float4 (*sWt4)[64] = reinterpret_cast<float4(*)[64]>(dsm + SM_WT);
    float4 (*su4)[8][SU_STRIDE] =
        reinterpret_cast<float4(*)[8][SU_STRIDE]>(dsm + SM_SU);
    float*  sWtF = reinterpret_cast<float*>(dsm + SM_WT);
    float*  sWoT = reinterpret_cast<float*>(dsm + SM_WO);
    float*  sbt  = reinterpret_cast<float*>(dsm + SM_BT);
    float*  sbo  = reinterpret_cast<float*>(dsm + SM_BO);

    int tid = threadIdx.x;
    int w = tid >> 5, lane = tid & 31;

    // ---- weight staging (coalesced reads, LDS-side transpose) ----
    // sWt4[ip][o] = W_tcn[o*192 + {6ip+0, 6ip+3, 6ip+1, 6ip+4}]
    for (int o = w; o < 64; o += K2_WARPS) {
        const float* wr = W_tcn + o * 192;
        #pragma unroll
        for (int j = 0; j < 6; j++) {
            int f = lane + 32 * j;
            float val = __ldg(wr + f);
            int ip = f / 6;
            int c  = f - ip * 6;               // 0..5
            int comp = (c == 0) ? 0 : (c == 3) ? 1 : (c == 1) ? 2 : (c == 4) ? 3 : -1;
            if (comp >= 0) sWtF[ip * 256 + o * 4 + comp] = val;
        }
    }
    for (int t = tid; t < 64 * PP; t += K2_THREADS) {
        float v = __ldg(W_out + t);
        int o = t / PP, p = t - o * PP;
        sWoT[p * WO_STRIDE + o] = v;
    }
    if (tid < 64) sbt[tid] = b_tcn[tid];
    if (tid < PP) sbo[tid] = b_out[tid];
    __syncthreads();

    int wg = blockIdx.x * K2_WARPS + w;       // 0..2515
    int nBase = wg * 4;                       // 10064 >= NN
    if (nBase >= NN) return;

    // ---- hoisted per-node metadata ----
    int deg[4];
    const int2* ep[4];
    #pragma unroll
    for (int m = 0; m < 4; m++) {
        int node = nBase + m;
        int nd = node < NN ? node : NN - 1;
        int d = g_cnt[nd];
        deg[m] = d > CAP ? CAP : d;
        ep[m] = g_edge + (size_t)nd * CAP;
    }

    // ---- gather 4 nodes, 8-edge groups (8 row-LDGs in flight) ----
    const float4* hb = reinterpret_cast<const float4*>(g_h16);  // 32 f4 / row
    #pragma unroll
    for (int m = 0; m < 4; m++) {
        float a[8];
        #pragma unroll
        for (int i = 0; i < 8; i++) a[i] = 0.0f;

        for (int k = 0; k < deg[m]; k += 8) {
            int   c[8];
            float v[8];
            #pragma unroll
            for (int j = 0; j < 8; j++) {
                int kk = k + j < deg[m] ? k + j : deg[m] - 1;
                int2 e = __ldg(ep[m] + kk);           // uniform, L1-hot
                c[j] = e.x;
                v[j] = (k + j < deg[m]) ? __int_as_float(e.y) : 0.0f;
            }
            float4 h4[8];
            #pragma unroll
            for (int j = 0; j < 8; j++)
                h4[j] = __ldg(hb + (size_t)c[j] * 32 + lane);
            #pragma unroll
            for (int j = 0; j < 8; j++) {
                const __half2* hp = reinterpret_cast<const __half2*>(&h4[j]);
                #pragma unroll
                for (int q = 0; q < 4; q++) {
                    float2 f = __half22float2(hp[q]);
                    a[q * 2 + 0] = fmaf(f.x, v[j], a[q * 2 + 0]);
                    a[q * 2 + 1] = fmaf(f.y, v[j], a[q * 2 + 1]);
                }
            }
        }

        // scatter relu(a) into su4: lane owns row values f = 8*lane + j
        #pragma unroll
        for (int j = 0; j < 8; j++) {
            int f = lane * 8 + j;
            int s = f >> 6;
            int h = f & 63;
            int b = s >> 1;
            int tap = s & 1;
            float* dst = reinterpret_cast<float*>(&su4[w][m * 2 + b][0]);
            dst[(h >> 1) * 4 + tap * 2 + (h & 1)] = fmaxf(a[j], 0.0f);
        }
    }
    if (lane < 4 && nBase + lane < NN) g_cnt[nBase + lane] = 0;  // self-clean
    __syncwarp();

    // ---- z-stage: 8 pairs, packed f32x2 (exact fp32), smem weights ----
    unsigned long long z0[8], z1[8];
    #pragma unroll
    for (int pp = 0; pp < 8; pp++) {
        z0[pp] = pack2(sbt[lane], 0.0f);
        z1[pp] = pack2(sbt[lane + 32], 0.0f);
    }
    #pragma unroll 4
    for (int ip = 0; ip < 32; ip++) {
        ulonglong2 wA = *reinterpret_cast<const ulonglong2*>(&sWt4[ip][lane]);
        ulonglong2 wB = *reinterpret_cast<const ulonglong2*>(&sWt4[ip][lane + 32]);
        #pragma unroll
        for (int pp = 0; pp < 8; pp++) {
            ulonglong2 u = *reinterpret_cast<const ulonglong2*>(&su4[w][pp][ip]);
            z0[pp] = fma2(u.x, wA.x, z0[pp]);   // tap0 pair
            z0[pp] = fma2(u.y, wA.y, z0[pp]);   // tap1 pair
            z1[pp] = fma2(u.x, wB.x, z1[pp]);
            z1[pp] = fma2(u.y, wB.y, z1[pp]);
        }
    }
    __syncwarp();
    #pragma unroll
    for (int pp = 0; pp < 8; pp++) {
        float* zf = reinterpret_cast<float*>(&su4[w][pp][0]);
        zf[lane]      = fmaxf(sum2(z0[pp]), 0.0f);
        zf[lane + 32] = fmaxf(sum2(z1[pp]), 0.0f);
    }
    __syncwarp();

    // ---- y-stage: 96 outputs (8 pairs x 12) in 3 lane-rounds ----
    #pragma unroll
    for (int r = 0; r < 3; r++) {
        int q = lane + r * 32;               // 0..95
        int pp = q / PP;
        int p  = q - pp * PP;
        unsigned long long y2 = pack2(sbo[p], 0.0f);
        const ulonglong2* z4 =
            reinterpret_cast<const ulonglong2*>(&su4[w][pp][0]);
        const ulonglong2* w4 =
            reinterpret_cast<const ulonglong2*>(sWoT + p * WO_STRIDE);
        #pragma unroll 4
        for (int oc = 0; oc < 16; oc++) {
            ulonglong2 zz = z4[oc];
            ulonglong2 ww = w4[oc];
            y2 = fma2(zz.x, ww.x, y2);
            y2 = fma2(zz.y, ww.y, y2);
        }
        int node = nBase + (pp >> 1);
        int b = pp & 1;
        if (node < NN)
            out[((size_t)b * PP + p) * NN + node] = sum2(y2);
    }
}

// ---------------------------------------------------------------------------
extern "C" void kernel_launch(void* const* d_in, const int* in_sizes, int n_in,
                              void* d_out, int out_size) {
    const float* x     = (const float*)d_in[0];
    const int*   row   = (const int*)  d_in[1];
    const int*   col   = (const int*)  d_in[2];
    const float* vals  = (const float*)d_in[3];
    const float* W_in  = (const float*)d_in[4];
    const float* b_in  = (const float*)d_in[5];
    const float* W_tcn = (const float*)d_in[6];
    const float* b_tcn = (const float*)d_in[7];
    const float* W_out = (const float*)d_in[8];
    const float* b_out = (const float*)d_in[9];
    float* out = (float*)d_out;

    static bool attr_set = false;
    if (!attr_set) {
        cudaFuncSetAttribute(k_gf,
                             cudaFuncAttributeMaxDynamicSharedMemorySize, SM_TOT);
        attr_set = true;
    }

    k_proj_bin<<<P_BLOCKS, 256>>>(x, W_in, b_in, row, col, vals);
    k_gf<<<148, K2_THREADS, SM_TOT>>>(W_tcn, b_tcn, W_out, b_out, out);
}